// round 15
// baseline (speedup 1.0000x reference)
#include <cuda_runtime.h>
#include <cuda_bf16.h>
#include <cuda_fp16.h>
#include <math.h>

#define B_  4
#define T_  4096
#define C_  1024
#define H_  64
#define BT  (B_*T_)

typedef unsigned int u32t;

// Pre-split bf16 hi/lo q,k (u32 = 2 packed bf16 cols; row = 32 u32 = 128B)
// q is PRE-SCALED by 0.125 (attention scale) at projection epilogue.
__device__ __align__(256) u32t g_qh[BT*32];
__device__ __align__(256) u32t g_ql[BT*32];
__device__ __align__(256) u32t g_kh[BT*32];
__device__ __align__(256) u32t g_kl[BT*32];
// V as packed fp16 (single precision term for PV)
__device__ __align__(256) u32t g_vf[BT*32];
// Pre-split W (3 x 64 x 1024 -> bf16 hi/lo, u32 = 2 cols; row = 512 u32)
__device__ __align__(256) u32t g_wh[192*512];
__device__ __align__(256) u32t g_wl[192*512];

// ---- helpers ---------------------------------------------------------------
__device__ __forceinline__ u32t smem_u32(const void* p) {
    u32t a;
    asm("{ .reg .u64 t; cvta.to.shared.u64 t, %1; cvt.u32.u64 %0, t; }"
        : "=r"(a) : "l"(p));
    return a;
}

__device__ __forceinline__ void split_pair(float f0, float f1, u32t& hi, u32t& lo) {
    __nv_bfloat16 h0 = __float2bfloat16(f0);
    __nv_bfloat16 h1 = __float2bfloat16(f1);
    __nv_bfloat16 l0 = __float2bfloat16(f0 - __bfloat162float(h0));
    __nv_bfloat16 l1 = __float2bfloat16(f1 - __bfloat162float(h1));
    hi = (u32t)__bfloat16_as_ushort(h0) | ((u32t)__bfloat16_as_ushort(h1) << 16);
    lo = (u32t)__bfloat16_as_ushort(l0) | ((u32t)__bfloat16_as_ushort(l1) << 16);
}

__device__ __forceinline__ u32t h2pack(float f0, float f1) {
    __half2 h = __floats2half2_rn(f0, f1);
    return *(u32t*)&h;
}

__device__ __forceinline__ void ldsm_x4(u32t* r, u32t addr) {
    asm volatile("ldmatrix.sync.aligned.m8n8.x4.shared.b16 {%0,%1,%2,%3}, [%4];"
                 : "=r"(r[0]), "=r"(r[1]), "=r"(r[2]), "=r"(r[3]) : "r"(addr));
}
__device__ __forceinline__ void ldsm_x4_t(u32t* r, u32t addr) {
    asm volatile("ldmatrix.sync.aligned.m8n8.x4.trans.shared.b16 {%0,%1,%2,%3}, [%4];"
                 : "=r"(r[0]), "=r"(r[1]), "=r"(r[2]), "=r"(r[3]) : "r"(addr));
}
__device__ __forceinline__ void mma16816(float* d, const u32t* a, u32t b0, u32t b1) {
    asm volatile("mma.sync.aligned.m16n8k16.row.col.f32.bf16.bf16.f32 "
                 "{%0,%1,%2,%3}, {%4,%5,%6,%7}, {%8,%9}, {%0,%1,%2,%3};"
                 : "+f"(d[0]), "+f"(d[1]), "+f"(d[2]), "+f"(d[3])
                 : "r"(a[0]), "r"(a[1]), "r"(a[2]), "r"(a[3]), "r"(b0), "r"(b1));
}
__device__ __forceinline__ void mma16816h(float* d, const u32t* a, u32t b0, u32t b1) {
    asm volatile("mma.sync.aligned.m16n8k16.row.col.f32.f16.f16.f32 "
                 "{%0,%1,%2,%3}, {%4,%5,%6,%7}, {%8,%9}, {%0,%1,%2,%3};"
                 : "+f"(d[0]), "+f"(d[1]), "+f"(d[2]), "+f"(d[3])
                 : "r"(a[0]), "r"(a[1]), "r"(a[2]), "r"(a[3]), "r"(b0), "r"(b1));
}

__device__ __forceinline__ void cpa16(u32t dst, const void* src) {
    asm volatile("cp.async.ca.shared.global [%0], [%1], 16;"
                 :: "r"(dst), "l"(src) : "memory");
}
__device__ __forceinline__ void cpa_commit() {
    asm volatile("cp.async.commit_group;" ::: "memory");
}
__device__ __forceinline__ void cpa_wait0() {
    asm volatile("cp.async.wait_group 0;" ::: "memory");
}
__device__ __forceinline__ void cpa_wait1() {
    asm volatile("cp.async.wait_group 1;" ::: "memory");
}

// async-copy one 64-row tile (64 x 128B) global -> smem (144B row stride)
__device__ __forceinline__ void stage_tile_async(const u32t* __restrict__ gsrc,
                                                 u32t dst_base, int ltid) {
    #pragma unroll
    for (int i = 0; i < 4; i++) {
        int id = ltid + 128*i;
        int row = id >> 3, seg = id & 7;
        cpa16(dst_base + row*144 + seg*16, gsrc + row*32 + seg*4);
    }
}

// ---------------------------------------------------------------------------
// Kernel 0: one-shot W split (3x64x1024 fp32 -> bf16 hi/lo packed u32)
// ---------------------------------------------------------------------------
__global__ __launch_bounds__(256) void wsplit_kernel(
        const float* __restrict__ Wq,
        const float* __restrict__ Wk,
        const float* __restrict__ Wv)
{
    const int id = blockIdx.x * 256 + threadIdx.x;
    const int row = id >> 9;
    const int c   = id & 511;
    const float* W = (row < 64) ? Wq : (row < 128) ? Wk : Wv;
    const float* p = W + (size_t)(row & 63) * C_ + 2*c;
    u32t hi, lo;
    split_pair(p[0], p[1], hi, lo);
    g_wh[id] = hi;
    g_wl[id] = lo;
}

// ---------------------------------------------------------------------------
// Kernel 1: QKV projection via bf16 split-precision HMMA. (unchanged)
// ---------------------------------------------------------------------------
#define PXB 0
#define PWB 40960
#define PROJ_SMEM (40960 + 2*30720)   // 102400

__device__ __forceinline__ void conv_x_chunk(const float4* vx, char* smem,
                                             int xoff, int tid) {
    #pragma unroll
    for (int i = 0; i < 4; i++) {
        int f4 = tid + 256*i; int r = f4 >> 3, c4 = (f4 & 7) * 4;
        u32t h0, l0, h1, l1;
        split_pair(vx[i].x, vx[i].y, h0, l0);
        split_pair(vx[i].z, vx[i].w, h1, l1);
        char* ph = smem + xoff + r*80 + c4*2;
        char* pl = smem + xoff + 10240 + r*80 + c4*2;
        *(u32t*)ph = h0; *(u32t*)(ph+4) = h1;
        *(u32t*)pl = l0; *(u32t*)(pl+4) = l1;
    }
}

__global__ __launch_bounds__(256) void proj_tc_kernel(const float* __restrict__ x)
{
    extern __shared__ char smem[];
    const u32t sb = smem_u32(smem);
    const int tid  = threadIdx.x;
    const int wid  = tid >> 5;
    const int lane = tid & 31;
    const int row0 = blockIdx.x * 128;

    float acc[24][4] = {};

    const int a_row = (lane & 15);
    const int a_c8  = ((lane >> 4) & 1) * 8;
    const int b_row = (lane & 7) + ((lane >> 4) & 1) * 8;
    const int b_c8  = ((lane >> 3) & 1) * 8;

    #pragma unroll
    for (int i = 0; i < 3; i++) {
        int id = tid + 256*i;
        int r = id >> 2, seg = id & 3;
        cpa16(sb + PWB + r*80 + seg*16,          g_wh + r*512 + seg*4);
        cpa16(sb + PWB + 15360 + r*80 + seg*16,  g_wl + r*512 + seg*4);
    }
    cpa_commit();

    float4 vx[4];
    #pragma unroll
    for (int i = 0; i < 4; i++) {
        int f4 = tid + 256*i; int r = f4 >> 3, c4 = (f4 & 7) * 4;
        vx[i] = *(const float4*)&x[(size_t)(row0 + r)*C_ + c4];
    }
    conv_x_chunk(vx, smem, PXB, tid);
    #pragma unroll
    for (int i = 0; i < 4; i++) {
        int f4 = tid + 256*i; int r = f4 >> 3, c4 = (f4 & 7) * 4;
        vx[i] = *(const float4*)&x[(size_t)(row0 + r)*C_ + 32 + c4];
    }

    for (int ch = 0; ch < 32; ch++) {
        const u32t wb = sb + PWB + (ch & 1) * 30720;
        const u32t xb = sb + PXB + (ch & 1) * 20480;

        cpa_wait0();
        __syncthreads();

        if (ch < 31) {
            const int c16 = (ch + 1) * 16;
            const u32t nb = sb + PWB + ((ch + 1) & 1) * 30720;
            #pragma unroll
            for (int i = 0; i < 3; i++) {
                int id = tid + 256*i;
                int r = id >> 2, seg = id & 3;
                cpa16(nb + r*80 + seg*16,         g_wh + r*512 + c16 + seg*4);
                cpa16(nb + 15360 + r*80 + seg*16, g_wl + r*512 + c16 + seg*4);
            }
            cpa_commit();
            conv_x_chunk(vx, smem, PXB + ((ch + 1) & 1) * 20480, tid);
            if (ch < 30) {
                const int k0n = (ch + 2) * 32;
                #pragma unroll
                for (int i = 0; i < 4; i++) {
                    int f4 = tid + 256*i; int r = f4 >> 3, c4 = (f4 & 7) * 4;
                    vx[i] = *(const float4*)&x[(size_t)(row0 + r)*C_ + k0n + c4];
                }
            }
        }

        u32t xh[2][4], xl[2][4];
        #pragma unroll
        for (int s = 0; s < 2; s++) {
            u32t ab = (u32t)((16*wid + a_row)*80 + (a_c8 + 16*s)*2);
            ldsm_x4(xh[s], xb + ab);
            ldsm_x4(xl[s], xb + 10240 + ab);
        }
        #pragma unroll
        for (int s = 0; s < 2; s++) {
            #pragma unroll
            for (int jp = 0; jp < 12; jp++) {
                u32t bb = (u32t)((16*jp + b_row)*80 + (b_c8 + 16*s)*2);
                u32t bh[4], bl[4];
                ldsm_x4(bh, wb + bb);
                ldsm_x4(bl, wb + 15360 + bb);
                mma16816(acc[2*jp],   xh[s], bh[0], bh[1]);
                mma16816(acc[2*jp+1], xh[s], bh[2], bh[3]);
                mma16816(acc[2*jp],   xh[s], bl[0], bl[1]);
                mma16816(acc[2*jp+1], xh[s], bl[2], bl[3]);
                mma16816(acc[2*jp],   xl[s], bh[0], bh[1]);
                mma16816(acc[2*jp+1], xl[s], bh[2], bh[3]);
            }
        }
    }

    const int q = lane & 3, r = lane >> 2;
    #pragma unroll
    for (int t = 0; t < 24; t++) {
        int uc = 4*(t & 7) + q;
        size_t rw = (size_t)(row0 + 16*wid + r);
        if (t < 8) {
            u32t h0, l0, h1, l1;
            split_pair(acc[t][0]*0.125f, acc[t][1]*0.125f, h0, l0);
            split_pair(acc[t][2]*0.125f, acc[t][3]*0.125f, h1, l1);
            g_qh[rw*32 + uc] = h0;      g_ql[rw*32 + uc] = l0;
            g_qh[(rw+8)*32 + uc] = h1;  g_ql[(rw+8)*32 + uc] = l1;
        } else if (t < 16) {
            u32t h0, l0, h1, l1;
            split_pair(acc[t][0], acc[t][1], h0, l0);
            split_pair(acc[t][2], acc[t][3], h1, l1);
            g_kh[rw*32 + uc] = h0;      g_kl[rw*32 + uc] = l0;
            g_kh[(rw+8)*32 + uc] = h1;  g_kl[(rw+8)*32 + uc] = l1;
        } else {
            g_vf[rw*32 + uc]     = h2pack(acc[t][0], acc[t][1]);
            g_vf[(rw+8)*32 + uc] = h2pack(acc[t][2], acc[t][3]);
        }
    }
}

// ---------------------------------------------------------------------------
// Kernel 2: flash-attention, software-pipelined: S(t+1) overlaps softmax(t).
// 2 warpgroups (256 thr), 3 KV buffers/group, shared Q, causal, paired.
// grid = (32, B), block = 256.
// ---------------------------------------------------------------------------
#define AQH 0
#define AQL 9216
#define AKV 18432
#define KVB 27648                      // one buffer: KH 0, KL 9216, VF 18432
#define GRPKV (3*KVB)                  // 82944 per group
#define ATTN_SMEM (18432 + 2*GRPKV)    // 184320
#define MRG_MD (AKV + GRPKV)           // merge scratch reuses group-1 KV
#define MRG_OD (MRG_MD + 2048)

// stage KV tile T into buffer index ((T)-tb)%3
#define STAGE_KV(T) do { \
    const size_t _kr = (size_t)(b*T_ + (T)*64) * 32; \
    u32t _nb = kvr + (((T) - tb) % 3) * KVB; \
    stage_tile_async(g_kh + _kr, _nb,         ltid); \
    stage_tile_async(g_kl + _kr, _nb + 9216,  ltid); \
    stage_tile_async(g_vf + _kr, _nb + 18432, ltid); \
} while (0)

// half S-phase: s-steps S0..S1 of S(t+1) into SFN
#define S_HALF(SFN, NBUF, S0, S1) do { \
    _Pragma("unroll") \
    for (int s = (S0); s < (S1); s++) { \
        _Pragma("unroll") \
        for (int jp = 0; jp < 4; jp++) { \
            u32t bb = (u32t)((16*jp + b_row)*144 + (b_c8 + 16*s)*2); \
            u32t bh[4], bl[4]; \
            ldsm_x4(bh, (NBUF) + bb); \
            ldsm_x4(bl, (NBUF) + 9216 + bb); \
            mma16816(SFN[2*jp],   qh[s], bh[0], bh[1]); \
            mma16816(SFN[2*jp+1], qh[s], bh[2], bh[3]); \
            mma16816(SFN[2*jp],   qh[s], bl[0], bl[1]); \
            mma16816(SFN[2*jp+1], qh[s], bl[2], bl[3]); \
            mma16816(SFN[2*jp],   ql[s], bh[0], bh[1]); \
            mma16816(SFN[2*jp+1], ql[s], bh[2], bh[3]); \
        } \
    } \
} while (0)

// one pipelined tile step: softmax+PV on SFC (tile T), S-MMA into SFN (tile T+1)
#define ATTN_BODY(T, SFC, SFN) do { \
    const int _t = (T); \
    const u32t cbuf = kvr + ((_t - tb) % 3) * KVB; \
    const bool have_next = (_t + 1 < te); \
    if (_t + 2 < te) { STAGE_KV(_t + 2); cpa_commit(); cpa_wait1(); } \
    else             { cpa_wait0(); } \
    asm volatile("bar.sync %0, 128;" :: "r"(g+1) : "memory"); \
    const u32t nbuf = kvr + ((_t + 1 - tb) % 3) * KVB; \
    if (have_next) { \
        _Pragma("unroll") \
        for (int j = 0; j < 8; j++) { \
            SFN[j][0] = 0.f; SFN[j][1] = 0.f; SFN[j][2] = 0.f; SFN[j][3] = 0.f; } \
    } \
    /* mask + row max on SFC (tile _t) */ \
    if (_t == ntm1) { \
        _Pragma("unroll") \
        for (int j = 0; j < 8; j++) { \
            int c = _t*64 + 8*j + 2*q; \
            if (c   > row0g) SFC[j][0] = -INFINITY; \
            if (c+1 > row0g) SFC[j][1] = -INFINITY; \
            if (c   > row1g) SFC[j][2] = -INFINITY; \
            if (c+1 > row1g) SFC[j][3] = -INFINITY; \
        } \
    } \
    float mx0 = -INFINITY, mx1 = -INFINITY; \
    _Pragma("unroll") \
    for (int j = 0; j < 8; j++) { \
        mx0 = fmaxf(mx0, fmaxf(SFC[j][0], SFC[j][1])); \
        mx1 = fmaxf(mx1, fmaxf(SFC[j][2], SFC[j][3])); \
    } \
    mx0 = fmaxf(mx0, __shfl_xor_sync(0xffffffffu, mx0, 1)); \
    mx0 = fmaxf(mx0, __shfl_xor_sync(0xffffffffu, mx0, 2)); \
    mx1 = fmaxf(mx1, __shfl_xor_sync(0xffffffffu, mx1, 1)); \
    mx1 = fmaxf(mx1, __shfl_xor_sync(0xffffffffu, mx1, 2)); \
    if (have_next) S_HALF(SFN, nbuf, 0, 2); \
    float mn0 = fmaxf(m_i0, mx0); \
    float mn1 = fmaxf(m_i1, mx1); \
    float al0 = __expf(m_i0 - mn0); \
    float al1 = __expf(m_i1 - mn1); \
    float rs0 = 0.f, rs1 = 0.f; \
    u32t pa[4][4]; \
    _Pragma("unroll") \
    for (int j = 0; j < 8; j++) { \
        float p0 = __expf(SFC[j][0] - mn0); \
        float p1 = __expf(SFC[j][1] - mn0); \
        float p2 = __expf(SFC[j][2] - mn1); \
        float p3 = __expf(SFC[j][3] - mn1); \
        rs0 += p0 + p1; rs1 += p2 + p3; \
        int t0 = j >> 1, hi2 = (j & 1) * 2; \
        pa[t0][hi2]   = h2pack(p0, p1); \
        pa[t0][hi2+1] = h2pack(p2, p3); \
    } \
    rs0 += __shfl_xor_sync(0xffffffffu, rs0, 1); \
    rs0 += __shfl_xor_sync(0xffffffffu, rs0, 2); \
    rs1 += __shfl_xor_sync(0xffffffffu, rs1, 1); \
    rs1 += __shfl_xor_sync(0xffffffffu, rs1, 2); \
    if (have_next) S_HALF(SFN, nbuf, 2, 4); \
    l_i0 = l_i0*al0 + rs0;  m_i0 = mn0; \
    l_i1 = l_i1*al1 + rs1;  m_i1 = mn1; \
    _Pragma("unroll") \
    for (int j = 0; j < 8; j++) { \
        o[j][0] *= al0; o[j][1] *= al0; \
        o[j][2] *= al1; o[j][3] *= al1; \
    } \
    _Pragma("unroll") \
    for (int t0 = 0; t0 < 4; t0++) { \
        _Pragma("unroll") \
        for (int jp = 0; jp < 4; jp++) { \
            u32t vb = (u32t)((16*t0 + v_row)*144 + (16*jp + v_c8)*2); \
            u32t vh[4]; \
            ldsm_x4_t(vh, cbuf + 18432 + vb); \
            mma16816h(o[2*jp],   pa[t0], vh[0], vh[1]); \
            mma16816h(o[2*jp+1], pa[t0], vh[2], vh[3]); \
        } \
    } \
    asm volatile("bar.sync %0, 128;" :: "r"(g+1) : "memory"); \
} while (0)

__global__ __launch_bounds__(256) void attn_tc_kernel(float* __restrict__ out)
{
    extern __shared__ char smem[];
    const u32t sb  = smem_u32(smem);
    const int tid  = threadIdx.x;
    const int g    = tid >> 7;          // warpgroup 0/1
    const int ltid = tid & 127;
    const int wid  = ltid >> 5;
    const int lane = tid & 31;
    const int b    = blockIdx.y;
    const int pr   = blockIdx.x;
    const int q    = lane & 3;
    const int r    = lane >> 2;

    const u32t kvr = sb + AKV + g * GRPKV;

    const int a_row = (lane & 15);
    const int a_c8  = ((lane >> 4) & 1) * 8;
    const int b_row = (lane & 7) + ((lane >> 4) & 1) * 8;
    const int b_c8  = ((lane >> 3) & 1) * 8;
    const int v_row = (lane & 7) + ((lane >> 3) & 1) * 8;
    const int v_c8  = ((lane >> 4) & 1) * 8;

    float* MD = (float*)(smem + MRG_MD);
    float* OD = (float*)(smem + MRG_OD);

    #pragma unroll 1
    for (int half = 0; half < 2; half++) {
        const int m0 = (half == 0 ? pr : 63 - pr) * 64;
        const int nt = m0/64 + 1;
        const int ntm1 = nt - 1;
        const int hsp = (nt + 1) >> 1;
        const int tb = g ? hsp : 0;
        const int te = g ? nt  : hsp;

        // prologue: group 0 stages shared Q; stage first two KV tiles
        if (g == 0) {
            const size_t qr = (size_t)(b*T_ + m0) * 32;
            stage_tile_async(g_qh + qr, sb + AQH, ltid);
            stage_tile_async(g_ql + qr, sb + AQL, ltid);
        }
        if (tb < te) STAGE_KV(tb);
        cpa_commit();
        if (tb + 1 < te) { STAGE_KV(tb + 1); cpa_commit(); cpa_wait1(); }
        else             { cpa_wait0(); }
        __syncthreads();     // Q + own buf0 visible

        u32t qh[4][4], ql[4][4];
        #pragma unroll
        for (int s = 0; s < 4; s++) {
            u32t ab = (u32t)((16*wid + a_row)*144 + (a_c8 + 16*s)*2);
            ldsm_x4(qh[s], sb + AQH + ab);
            ldsm_x4(ql[s], sb + AQL + ab);
        }

        float o[8][4] = {};
        float m_i0 = -INFINITY, m_i1 = -INFINITY, l_i0 = 0.f, l_i1 = 0.f;
        const int row0g = m0 + 16*wid + r;
        const int row1g = row0g + 8;

        float sfA[8][4], sfB[8][4];

        if (tb < te) {
            // compute S(tb) into sfA
            #pragma unroll
            for (int j = 0; j < 8; j++) {
                sfA[j][0] = 0.f; sfA[j][1] = 0.f; sfA[j][2] = 0.f; sfA[j][3] = 0.f; }
            S_HALF(sfA, kvr, 0, 4);

            // pipelined loop, manual unroll-2 for sf ping-pong
            int t = tb;
            #pragma unroll 1
            while (t < te) {
                ATTN_BODY(t, sfA, sfB);
                if (t + 1 < te) ATTN_BODY(t + 1, sfB, sfA);
                t += 2;
            }
        }

        // ---- merge partials across the two groups ----
        __syncthreads();
        if (g == 1) {
            MD[ltid*4+0] = m_i0; MD[ltid*4+1] = m_i1;
            MD[ltid*4+2] = l_i0; MD[ltid*4+3] = l_i1;
            #pragma unroll
            for (int j = 0; j < 8; j++)
                #pragma unroll
                for (int e = 0; e < 4; e++)
                    OD[ltid*32 + j*4 + e] = o[j][e];
        }
        __syncthreads();
        if (g == 0) {
            float m1_0 = MD[ltid*4+0], m1_1 = MD[ltid*4+1];
            float l1_0 = MD[ltid*4+2], l1_1 = MD[ltid*4+3];
            float mn0 = fmaxf(m_i0, m1_0);
            float mn1 = fmaxf(m_i1, m1_1);
            float a0 = __expf(m_i0 - mn0), b0 = __expf(m1_0 - mn0);
            float a1 = __expf(m_i1 - mn1), b1 = __expf(m1_1 - mn1);
            float lt0 = l_i0*a0 + l1_0*b0;
            float lt1 = l_i1*a1 + l1_1*b1;
            float inv0 = 1.0f / lt0;
            float inv1 = 1.0f / lt1;
            float* ob = out + (size_t)(b*T_) * H_;
            #pragma unroll
            for (int j = 0; j < 8; j++) {
                int col = 8*j + 2*q;
                float o0 = (o[j][0]*a0 + OD[ltid*32 + j*4 + 0]*b0) * inv0;
                float o1 = (o[j][1]*a0 + OD[ltid*32 + j*4 + 1]*b0) * inv0;
                float o2 = (o[j][2]*a1 + OD[ltid*32 + j*4 + 2]*b1) * inv1;
                float o3 = (o[j][3]*a1 + OD[ltid*32 + j*4 + 3]*b1) * inv1;
                *(float2*)&ob[(size_t)row0g*H_ + col] = make_float2(o0, o1);
                *(float2*)&ob[(size_t)row1g*H_ + col] = make_float2(o2, o3);
            }
        }
        __syncthreads();
    }
}

// ---------------------------------------------------------------------------
extern "C" void kernel_launch(void* const* d_in, const int* in_sizes, int n_in,
                              void* d_out, int out_size)
{
    const float* x  = (const float*)d_in[0];
    const float* Wq = (const float*)d_in[1];
    const float* Wk = (const float*)d_in[2];
    const float* Wv = (const float*)d_in[3];
    float* out = (float*)d_out;

    cudaFuncSetAttribute(proj_tc_kernel,
                         cudaFuncAttributeMaxDynamicSharedMemorySize, PROJ_SMEM);
    cudaFuncSetAttribute(attn_tc_kernel,
                         cudaFuncAttributeMaxDynamicSharedMemorySize, ATTN_SMEM);

    wsplit_kernel<<<384, 256>>>(Wq, Wk, Wv);
    proj_tc_kernel<<<BT/128, 256, PROJ_SMEM>>>(x);
    attn_tc_kernel<<<dim3(32, B_), 256, ATTN_SMEM>>>(out);
}

// round 16
// speedup vs baseline: 1.8037x; 1.8037x over previous
#include <cuda_runtime.h>
#include <cuda_bf16.h>
#include <cuda_fp16.h>
#include <math.h>

#define B_  4
#define T_  4096
#define C_  1024
#define H_  64
#define BT  (B_*T_)

typedef unsigned int u32t;

// q,k,v as packed fp16 (u32 = 2 cols; row = 32 u32 = 128B).
// q is PRE-SCALED by 0.125 (attention scale) at projection epilogue.
__device__ __align__(256) u32t g_qf[BT*32];
__device__ __align__(256) u32t g_kf[BT*32];
__device__ __align__(256) u32t g_vf[BT*32];
// Pre-split W (3 x 64 x 1024 -> bf16 hi/lo, u32 = 2 cols; row = 512 u32)
__device__ __align__(256) u32t g_wh[192*512];
__device__ __align__(256) u32t g_wl[192*512];

// ---- helpers ---------------------------------------------------------------
__device__ __forceinline__ u32t smem_u32(const void* p) {
    u32t a;
    asm("{ .reg .u64 t; cvta.to.shared.u64 t, %1; cvt.u32.u64 %0, t; }"
        : "=r"(a) : "l"(p));
    return a;
}

__device__ __forceinline__ void split_pair(float f0, float f1, u32t& hi, u32t& lo) {
    __nv_bfloat16 h0 = __float2bfloat16(f0);
    __nv_bfloat16 h1 = __float2bfloat16(f1);
    __nv_bfloat16 l0 = __float2bfloat16(f0 - __bfloat162float(h0));
    __nv_bfloat16 l1 = __float2bfloat16(f1 - __bfloat162float(h1));
    hi = (u32t)__bfloat16_as_ushort(h0) | ((u32t)__bfloat16_as_ushort(h1) << 16);
    lo = (u32t)__bfloat16_as_ushort(l0) | ((u32t)__bfloat16_as_ushort(l1) << 16);
}

__device__ __forceinline__ u32t h2pack(float f0, float f1) {
    __half2 h = __floats2half2_rn(f0, f1);
    return *(u32t*)&h;
}

__device__ __forceinline__ void ldsm_x4(u32t* r, u32t addr) {
    asm volatile("ldmatrix.sync.aligned.m8n8.x4.shared.b16 {%0,%1,%2,%3}, [%4];"
                 : "=r"(r[0]), "=r"(r[1]), "=r"(r[2]), "=r"(r[3]) : "r"(addr));
}
__device__ __forceinline__ void ldsm_x4_t(u32t* r, u32t addr) {
    asm volatile("ldmatrix.sync.aligned.m8n8.x4.trans.shared.b16 {%0,%1,%2,%3}, [%4];"
                 : "=r"(r[0]), "=r"(r[1]), "=r"(r[2]), "=r"(r[3]) : "r"(addr));
}
__device__ __forceinline__ void mma16816(float* d, const u32t* a, u32t b0, u32t b1) {
    asm volatile("mma.sync.aligned.m16n8k16.row.col.f32.bf16.bf16.f32 "
                 "{%0,%1,%2,%3}, {%4,%5,%6,%7}, {%8,%9}, {%0,%1,%2,%3};"
                 : "+f"(d[0]), "+f"(d[1]), "+f"(d[2]), "+f"(d[3])
                 : "r"(a[0]), "r"(a[1]), "r"(a[2]), "r"(a[3]), "r"(b0), "r"(b1));
}
__device__ __forceinline__ void mma16816h(float* d, const u32t* a, u32t b0, u32t b1) {
    asm volatile("mma.sync.aligned.m16n8k16.row.col.f32.f16.f16.f32 "
                 "{%0,%1,%2,%3}, {%4,%5,%6,%7}, {%8,%9}, {%0,%1,%2,%3};"
                 : "+f"(d[0]), "+f"(d[1]), "+f"(d[2]), "+f"(d[3])
                 : "r"(a[0]), "r"(a[1]), "r"(a[2]), "r"(a[3]), "r"(b0), "r"(b1));
}

__device__ __forceinline__ void cpa16(u32t dst, const void* src) {
    asm volatile("cp.async.ca.shared.global [%0], [%1], 16;"
                 :: "r"(dst), "l"(src) : "memory");
}
__device__ __forceinline__ void cpa_commit() {
    asm volatile("cp.async.commit_group;" ::: "memory");
}
__device__ __forceinline__ void cpa_wait0() {
    asm volatile("cp.async.wait_group 0;" ::: "memory");
}
__device__ __forceinline__ void cpa_wait1() {
    asm volatile("cp.async.wait_group 1;" ::: "memory");
}

// async-copy one 64-row fp16 tile (64 x 128B) global -> smem (144B row stride)
__device__ __forceinline__ void stage_tile_async(const u32t* __restrict__ gsrc,
                                                 u32t dst_base, int ltid) {
    #pragma unroll
    for (int i = 0; i < 4; i++) {
        int id = ltid + 128*i;
        int row = id >> 3, seg = id & 7;
        cpa16(dst_base + row*144 + seg*16, gsrc + row*32 + seg*4);
    }
}

// ---------------------------------------------------------------------------
// Kernel 0: one-shot W split (3x64x1024 fp32 -> bf16 hi/lo packed u32)
// ---------------------------------------------------------------------------
__global__ __launch_bounds__(256) void wsplit_kernel(
        const float* __restrict__ Wq,
        const float* __restrict__ Wk,
        const float* __restrict__ Wv)
{
    const int id = blockIdx.x * 256 + threadIdx.x;
    const int row = id >> 9;
    const int c   = id & 511;
    const float* W = (row < 64) ? Wq : (row < 128) ? Wk : Wv;
    const float* p = W + (size_t)(row & 63) * C_ + 2*c;
    u32t hi, lo;
    split_pair(p[0], p[1], hi, lo);
    g_wh[id] = hi;
    g_wl[id] = lo;
}

// ---------------------------------------------------------------------------
// Kernel 1: QKV projection via bf16 split-precision HMMA (accurate q,k,v),
// results stored as packed fp16. grid = BT/128, block = 256.
// ---------------------------------------------------------------------------
#define PXB 0
#define PWB 40960
#define PROJ_SMEM (40960 + 2*30720)   // 102400

__device__ __forceinline__ void conv_x_chunk(const float4* vx, char* smem,
                                             int xoff, int tid) {
    #pragma unroll
    for (int i = 0; i < 4; i++) {
        int f4 = tid + 256*i; int r = f4 >> 3, c4 = (f4 & 7) * 4;
        u32t h0, l0, h1, l1;
        split_pair(vx[i].x, vx[i].y, h0, l0);
        split_pair(vx[i].z, vx[i].w, h1, l1);
        char* ph = smem + xoff + r*80 + c4*2;
        char* pl = smem + xoff + 10240 + r*80 + c4*2;
        *(u32t*)ph = h0; *(u32t*)(ph+4) = h1;
        *(u32t*)pl = l0; *(u32t*)(pl+4) = l1;
    }
}

__global__ __launch_bounds__(256) void proj_tc_kernel(const float* __restrict__ x)
{
    extern __shared__ char smem[];
    const u32t sb = smem_u32(smem);
    const int tid  = threadIdx.x;
    const int wid  = tid >> 5;
    const int lane = tid & 31;
    const int row0 = blockIdx.x * 128;

    float acc[24][4] = {};

    const int a_row = (lane & 15);
    const int a_c8  = ((lane >> 4) & 1) * 8;
    const int b_row = (lane & 7) + ((lane >> 4) & 1) * 8;
    const int b_c8  = ((lane >> 3) & 1) * 8;

    #pragma unroll
    for (int i = 0; i < 3; i++) {
        int id = tid + 256*i;
        int r = id >> 2, seg = id & 3;
        cpa16(sb + PWB + r*80 + seg*16,          g_wh + r*512 + seg*4);
        cpa16(sb + PWB + 15360 + r*80 + seg*16,  g_wl + r*512 + seg*4);
    }
    cpa_commit();

    float4 vx[4];
    #pragma unroll
    for (int i = 0; i < 4; i++) {
        int f4 = tid + 256*i; int r = f4 >> 3, c4 = (f4 & 7) * 4;
        vx[i] = *(const float4*)&x[(size_t)(row0 + r)*C_ + c4];
    }
    conv_x_chunk(vx, smem, PXB, tid);
    #pragma unroll
    for (int i = 0; i < 4; i++) {
        int f4 = tid + 256*i; int r = f4 >> 3, c4 = (f4 & 7) * 4;
        vx[i] = *(const float4*)&x[(size_t)(row0 + r)*C_ + 32 + c4];
    }

    for (int ch = 0; ch < 32; ch++) {
        const u32t wb = sb + PWB + (ch & 1) * 30720;
        const u32t xb = sb + PXB + (ch & 1) * 20480;

        cpa_wait0();
        __syncthreads();

        if (ch < 31) {
            const int c16 = (ch + 1) * 16;
            const u32t nb = sb + PWB + ((ch + 1) & 1) * 30720;
            #pragma unroll
            for (int i = 0; i < 3; i++) {
                int id = tid + 256*i;
                int r = id >> 2, seg = id & 3;
                cpa16(nb + r*80 + seg*16,         g_wh + r*512 + c16 + seg*4);
                cpa16(nb + 15360 + r*80 + seg*16, g_wl + r*512 + c16 + seg*4);
            }
            cpa_commit();
            conv_x_chunk(vx, smem, PXB + ((ch + 1) & 1) * 20480, tid);
            if (ch < 30) {
                const int k0n = (ch + 2) * 32;
                #pragma unroll
                for (int i = 0; i < 4; i++) {
                    int f4 = tid + 256*i; int r = f4 >> 3, c4 = (f4 & 7) * 4;
                    vx[i] = *(const float4*)&x[(size_t)(row0 + r)*C_ + k0n + c4];
                }
            }
        }

        u32t xh[2][4], xl[2][4];
        #pragma unroll
        for (int s = 0; s < 2; s++) {
            u32t ab = (u32t)((16*wid + a_row)*80 + (a_c8 + 16*s)*2);
            ldsm_x4(xh[s], xb + ab);
            ldsm_x4(xl[s], xb + 10240 + ab);
        }
        #pragma unroll
        for (int s = 0; s < 2; s++) {
            #pragma unroll
            for (int jp = 0; jp < 12; jp++) {
                u32t bb = (u32t)((16*jp + b_row)*80 + (b_c8 + 16*s)*2);
                u32t bh[4], bl[4];
                ldsm_x4(bh, wb + bb);
                ldsm_x4(bl, wb + 15360 + bb);
                mma16816(acc[2*jp],   xh[s], bh[0], bh[1]);
                mma16816(acc[2*jp+1], xh[s], bh[2], bh[3]);
                mma16816(acc[2*jp],   xh[s], bl[0], bl[1]);
                mma16816(acc[2*jp+1], xh[s], bl[2], bl[3]);
                mma16816(acc[2*jp],   xl[s], bh[0], bh[1]);
                mma16816(acc[2*jp+1], xl[s], bh[2], bh[3]);
            }
        }
    }

    // epilogue: store q (x0.125), k, v as packed fp16
    const int q = lane & 3, r = lane >> 2;
    #pragma unroll
    for (int t = 0; t < 24; t++) {
        int uc = 4*(t & 7) + q;
        size_t rw = (size_t)(row0 + 16*wid + r);
        if (t < 8) {
            g_qf[rw*32 + uc]     = h2pack(acc[t][0]*0.125f, acc[t][1]*0.125f);
            g_qf[(rw+8)*32 + uc] = h2pack(acc[t][2]*0.125f, acc[t][3]*0.125f);
        } else if (t < 16) {
            g_kf[rw*32 + uc]     = h2pack(acc[t][0], acc[t][1]);
            g_kf[(rw+8)*32 + uc] = h2pack(acc[t][2], acc[t][3]);
        } else {
            g_vf[rw*32 + uc]     = h2pack(acc[t][0], acc[t][1]);
            g_vf[(rw+8)*32 + uc] = h2pack(acc[t][2], acc[t][3]);
        }
    }
}

// ---------------------------------------------------------------------------
// Kernel 2: flash-attention, all-fp16 MMA (S single-term, PV single-term).
// Causal, paired query tiles, KV split across 2 warpgroups, double-buffered
// cp.async staging. grid = (32, B), block = 256.
// ---------------------------------------------------------------------------
#define AQF 0
#define AKV 9216                       // per-buffer: KF 0, VF 9216
#define KVB 18432
#define GRPKV (2*KVB)                  // 36864 per group
#define ATTN_SMEM (9216 + 2*GRPKV)     // 82944
#define MRG_MD (AKV + GRPKV)           // merge scratch reuses group-1 KV
#define MRG_OD (MRG_MD + 2048)

__global__ __launch_bounds__(256) void attn_tc_kernel(float* __restrict__ out)
{
    extern __shared__ char smem[];
    const u32t sb  = smem_u32(smem);
    const int tid  = threadIdx.x;
    const int g    = tid >> 7;
    const int ltid = tid & 127;
    const int wid  = ltid >> 5;
    const int lane = tid & 31;
    const int b    = blockIdx.y;
    const int pr   = blockIdx.x;
    const int q    = lane & 3;
    const int r    = lane >> 2;

    const u32t kvr = sb + AKV + g * GRPKV;

    const int a_row = (lane & 15);
    const int a_c8  = ((lane >> 4) & 1) * 8;
    const int b_row = (lane & 7) + ((lane >> 4) & 1) * 8;
    const int b_c8  = ((lane >> 3) & 1) * 8;
    const int v_row = (lane & 7) + ((lane >> 3) & 1) * 8;
    const int v_c8  = ((lane >> 4) & 1) * 8;

    float* MD = (float*)(smem + MRG_MD);
    float* OD = (float*)(smem + MRG_OD);

    #pragma unroll 1
    for (int half = 0; half < 2; half++) {
        const int m0 = (half == 0 ? pr : 63 - pr) * 64;
        const int nt = m0/64 + 1;
        const int hsp = (nt + 1) >> 1;
        const int tb = g ? hsp : 0;
        const int te = g ? nt  : hsp;

        // prologue: group 0 stages shared Q; each group stages its first tile
        {
            if (g == 0) {
                const size_t qr = (size_t)(b*T_ + m0) * 32;
                stage_tile_async(g_qf + qr, sb + AQF, ltid);
            }
            if (tb < te) {
                const size_t kr = (size_t)(b*T_ + tb*64) * 32;
                stage_tile_async(g_kf + kr, kvr,        ltid);
                stage_tile_async(g_vf + kr, kvr + 9216, ltid);
            }
            cpa_commit();
            cpa_wait0();
            __syncthreads();     // Q visible to all groups
        }

        u32t qf[4][4];
        #pragma unroll
        for (int s = 0; s < 4; s++) {
            u32t ab = (u32t)((16*wid + a_row)*144 + (a_c8 + 16*s)*2);
            ldsm_x4(qf[s], sb + AQF + ab);
        }

        float o[8][4] = {};
        float m_i0 = -INFINITY, m_i1 = -INFINITY, l_i0 = 0.f, l_i1 = 0.f;
        const int row0g = m0 + 16*wid + r;
        const int row1g = row0g + 8;

        for (int t = tb; t < te; t++) {
            const int n0 = t * 64;
            const int cur = (t - tb) & 1;
            const u32t cb = kvr + cur * KVB;

            if (t + 1 < te) {
                const size_t kr = (size_t)(b*T_ + (t+1)*64) * 32;
                u32t nb = kvr + (cur ^ 1) * KVB;
                stage_tile_async(g_kf + kr, nb,        ltid);
                stage_tile_async(g_vf + kr, nb + 9216, ltid);
                cpa_commit();
                cpa_wait1();
            } else {
                cpa_wait0();
            }
            asm volatile("bar.sync %0, 128;" :: "r"(g+1) : "memory");

            // ---- S = Q K^T (fp16 single-term) ----
            float sf[8][4] = {};
            #pragma unroll
            for (int s = 0; s < 4; s++) {
                #pragma unroll
                for (int jp = 0; jp < 4; jp++) {
                    u32t bb = (u32t)((16*jp + b_row)*144 + (b_c8 + 16*s)*2);
                    u32t bh[4];
                    ldsm_x4(bh, cb + bb);
                    mma16816h(sf[2*jp],   qf[s], bh[0], bh[1]);
                    mma16816h(sf[2*jp+1], qf[s], bh[2], bh[3]);
                }
            }

            // ---- causal mask (scale pre-folded into Q) ----
            if (n0 == m0) {
                #pragma unroll
                for (int j = 0; j < 8; j++) {
                    int c = n0 + 8*j + 2*q;
                    if (c   > row0g) sf[j][0] = -INFINITY;
                    if (c+1 > row0g) sf[j][1] = -INFINITY;
                    if (c   > row1g) sf[j][2] = -INFINITY;
                    if (c+1 > row1g) sf[j][3] = -INFINITY;
                }
            }

            // ---- online softmax ----
            float mx0 = -INFINITY, mx1 = -INFINITY;
            #pragma unroll
            for (int j = 0; j < 8; j++) {
                mx0 = fmaxf(mx0, fmaxf(sf[j][0], sf[j][1]));
                mx1 = fmaxf(mx1, fmaxf(sf[j][2], sf[j][3]));
            }
            mx0 = fmaxf(mx0, __shfl_xor_sync(0xffffffffu, mx0, 1));
            mx0 = fmaxf(mx0, __shfl_xor_sync(0xffffffffu, mx0, 2));
            mx1 = fmaxf(mx1, __shfl_xor_sync(0xffffffffu, mx1, 1));
            mx1 = fmaxf(mx1, __shfl_xor_sync(0xffffffffu, mx1, 2));
            float mn0 = fmaxf(m_i0, mx0);
            float mn1 = fmaxf(m_i1, mx1);
            float al0 = __expf(m_i0 - mn0);
            float al1 = __expf(m_i1 - mn1);

            float rs0 = 0.f, rs1 = 0.f;
            u32t pa[4][4];
            #pragma unroll
            for (int j = 0; j < 8; j++) {
                float p0 = __expf(sf[j][0] - mn0);
                float p1 = __expf(sf[j][1] - mn0);
                float p2 = __expf(sf[j][2] - mn1);
                float p3 = __expf(sf[j][3] - mn1);
                rs0 += p0 + p1; rs1 += p2 + p3;
                int t0 = j >> 1, hi2 = (j & 1) * 2;
                pa[t0][hi2]   = h2pack(p0, p1);
                pa[t0][hi2+1] = h2pack(p2, p3);
            }
            rs0 += __shfl_xor_sync(0xffffffffu, rs0, 1);
            rs0 += __shfl_xor_sync(0xffffffffu, rs0, 2);
            rs1 += __shfl_xor_sync(0xffffffffu, rs1, 1);
            rs1 += __shfl_xor_sync(0xffffffffu, rs1, 2);
            l_i0 = l_i0*al0 + rs0;  m_i0 = mn0;
            l_i1 = l_i1*al1 + rs1;  m_i1 = mn1;
            #pragma unroll
            for (int j = 0; j < 8; j++) {
                o[j][0] *= al0; o[j][1] *= al0;
                o[j][2] *= al1; o[j][3] *= al1;
            }

            // ---- O += P V (fp16) ----
            #pragma unroll
            for (int t0 = 0; t0 < 4; t0++) {
                #pragma unroll
                for (int jp = 0; jp < 4; jp++) {
                    u32t vb = (u32t)((16*t0 + v_row)*144 + (16*jp + v_c8)*2);
                    u32t vh[4];
                    ldsm_x4_t(vh, cb + 9216 + vb);
                    mma16816h(o[2*jp],   pa[t0], vh[0], vh[1]);
                    mma16816h(o[2*jp+1], pa[t0], vh[2], vh[3]);
                }
            }
            asm volatile("bar.sync %0, 128;" :: "r"(g+1) : "memory");
        }

        // ---- merge partials across the two groups ----
        __syncthreads();
        if (g == 1) {
            MD[ltid*4+0] = m_i0; MD[ltid*4+1] = m_i1;
            MD[ltid*4+2] = l_i0; MD[ltid*4+3] = l_i1;
            #pragma unroll
            for (int j = 0; j < 8; j++)
                #pragma unroll
                for (int e = 0; e < 4; e++)
                    OD[ltid*32 + j*4 + e] = o[j][e];
        }
        __syncthreads();
        if (g == 0) {
            float m1_0 = MD[ltid*4+0], m1_1 = MD[ltid*4+1];
            float l1_0 = MD[ltid*4+2], l1_1 = MD[ltid*4+3];
            float mn0 = fmaxf(m_i0, m1_0);
            float mn1 = fmaxf(m_i1, m1_1);
            float a0 = __expf(m_i0 - mn0), b0 = __expf(m1_0 - mn0);
            float a1 = __expf(m_i1 - mn1), b1 = __expf(m1_1 - mn1);
            float lt0 = l_i0*a0 + l1_0*b0;
            float lt1 = l_i1*a1 + l1_1*b1;
            float inv0 = 1.0f / lt0;
            float inv1 = 1.0f / lt1;
            float* ob = out + (size_t)(b*T_) * H_;
            #pragma unroll
            for (int j = 0; j < 8; j++) {
                int col = 8*j + 2*q;
                float o0 = (o[j][0]*a0 + OD[ltid*32 + j*4 + 0]*b0) * inv0;
                float o1 = (o[j][1]*a0 + OD[ltid*32 + j*4 + 1]*b0) * inv0;
                float o2 = (o[j][2]*a1 + OD[ltid*32 + j*4 + 2]*b1) * inv1;
                float o3 = (o[j][3]*a1 + OD[ltid*32 + j*4 + 3]*b1) * inv1;
                *(float2*)&ob[(size_t)row0g*H_ + col] = make_float2(o0, o1);
                *(float2*)&ob[(size_t)row1g*H_ + col] = make_float2(o2, o3);
            }
        }
        __syncthreads();
    }
}

// ---------------------------------------------------------------------------
extern "C" void kernel_launch(void* const* d_in, const int* in_sizes, int n_in,
                              void* d_out, int out_size)
{
    const float* x  = (const float*)d_in[0];
    const float* Wq = (const float*)d_in[1];
    const float* Wk = (const float*)d_in[2];
    const float* Wv = (const float*)d_in[3];
    float* out = (float*)d_out;

    cudaFuncSetAttribute(proj_tc_kernel,
                         cudaFuncAttributeMaxDynamicSharedMemorySize, PROJ_SMEM);
    cudaFuncSetAttribute(attn_tc_kernel,
                         cudaFuncAttributeMaxDynamicSharedMemorySize, ATTN_SMEM);

    wsplit_kernel<<<384, 256>>>(Wq, Wk, Wv);
    proj_tc_kernel<<<BT/128, 256, PROJ_SMEM>>>(x);
    attn_tc_kernel<<<dim3(32, B_), 256, ATTN_SMEM>>>(out);
}